// round 4
// baseline (speedup 1.0000x reference)
#include <cuda_runtime.h>
#include <cstdint>

#define IN_C   64
#define OUT_C  64
#define KMAX   27
#define MAX_E  2000000
#define BATCH  16
#define PADCAP (MAX_E + KMAX * BATCH + BATCH)

// weight smem layout: [k][g][c][d]; group stride padded so the per-c LDS.128
// (lanes = h*16 + gs*4 + dq) is conflict-free in each 8-lane sub-request.
#define WGS  272                 // 256 + 16 pad
#define WKS  (4 * WGS)           // 1088
#define WTOT (KMAX * WKS)        // 29376 floats = 117504 B

// ---- scratch (device globals; no allocation allowed) ----
__device__ int g_hist[KMAX];
__device__ int g_cursor[KMAX];
__device__ int g_sorted[PADCAP];

// ---- f32x2 helpers (packed fp32, 2 FMA/instr) ----
__device__ __forceinline__ unsigned long long pack_dup(float x) {
    unsigned long long r; unsigned xi = __float_as_uint(x);
    asm("mov.b64 %0, {%1, %1};" : "=l"(r) : "r"(xi));
    return r;
}
__device__ __forceinline__ unsigned long long fma2(unsigned long long a,
                                                   unsigned long long b,
                                                   unsigned long long c) {
    unsigned long long d;
    asm("fma.rn.f32x2 %0, %1, %2, %3;" : "=l"(d) : "l"(a), "l"(b), "l"(c));
    return d;
}
__device__ __forceinline__ void unpack2(unsigned long long v, float& lo, float& hi) {
    asm("mov.b64 {%0, %1}, %2;" : "=f"(lo), "=f"(hi) : "l"(v));
}

// ---- 1) fused: out = bias, g_sorted = -1, block-aggregated k histogram ----
__global__ void init_all(float4* __restrict__ out, const float* __restrict__ bias,
                         const int* __restrict__ ka, int n4, int preN, int E) {
    __shared__ float4 b4[16];
    __shared__ int h[KMAX];
    if (threadIdx.x < 16) b4[threadIdx.x] = reinterpret_cast<const float4*>(bias)[threadIdx.x];
    if (threadIdx.x < KMAX) h[threadIdx.x] = 0;
    __syncthreads();
    int idx = blockIdx.x * blockDim.x + threadIdx.x;
    if (idx < n4)   out[idx] = b4[idx & 15];
    if (idx < preN) g_sorted[idx] = -1;
    if (idx < E)    atomicAdd(&h[ka[idx]], 1);
    __syncthreads();
    if (threadIdx.x < KMAX && h[threadIdx.x]) atomicAdd(&g_hist[threadIdx.x], h[threadIdx.x]);
}

// ---- 2) warp exclusive scan of BATCH-aligned bucket sizes; clears g_hist
//         afterwards so the next graph replay starts from zero ----
__global__ void scan_k() {
    int lane = threadIdx.x;
    int v = (lane < KMAX) ? ((g_hist[lane] + BATCH - 1) & ~(BATCH - 1)) : 0;
    int s = v;
    #pragma unroll
    for (int o = 1; o < 32; o <<= 1) {
        int t = __shfl_up_sync(0xffffffffu, s, o);
        if (lane >= o) s += t;
    }
    if (lane < KMAX) {
        g_cursor[lane] = s - v;   // exclusive, aligned starts
        g_hist[lane] = 0;         // reset for next replay
    }
}

// ---- 3) scatter edge ids into k-sorted order (block-aggregated atomics) ----
// One 256-edge tile per CTA (full grid, no grid-stride: hides sync latency).
__global__ void scatter_k(const int* __restrict__ ka, int E) {
    __shared__ int cnt[KMAX];
    __shared__ int bas[KMAX];
    int idx = blockIdx.x * blockDim.x + threadIdx.x;
    if (threadIdx.x < KMAX) cnt[threadIdx.x] = 0;
    __syncthreads();
    int kv = 0, my = 0;
    bool v = idx < E;
    if (v) { kv = ka[idx]; my = atomicAdd(&cnt[kv], 1); }
    __syncthreads();
    if (threadIdx.x < KMAX && cnt[threadIdx.x])
        bas[threadIdx.x] = atomicAdd(&g_cursor[threadIdx.x], cnt[threadIdx.x]);
    __syncthreads();
    if (v) g_sorted[bas[kv] + my] = idx;
}

// ---- 4) fused conv ----
// Warp batch = 16 edges (k-uniform by construction).
// Lane = h*16 + gs*4 + dq: owns output d-quad dq of group gs for the 8 edges
// of half h. Weights: one LDS.128 per c per es-half (256B distinct/warp).
// x read directly from GMEM in two es-halves (register economy -> 24 warps/SM).
__global__ __launch_bounds__(768, 1) void conv_k(
    const float* __restrict__ x, const int* __restrict__ ia,
    const int* __restrict__ ja, const int* __restrict__ ka,
    const float* __restrict__ wgt, float* __restrict__ out, int nB)
{
    extern __shared__ float sw[];

    // cooperative weight load: src coalesced, dst scattered (once per CTA)
    for (int idx = threadIdx.x; idx < IN_C * (OUT_C / 4) * KMAX; idx += blockDim.x) {
        int k = idx % KMAX;
        int r = idx / KMAX;          // r = (g*16+c)*16 + d
        int d = r & 15;
        int c = (r >> 4) & 15;
        int g = r >> 8;
        sw[k * WKS + g * WGS + c * 16 + d] = wgt[idx];
    }
    __syncthreads();

    int lane = threadIdx.x & 31;
    int warp = threadIdx.x >> 5;
    int dq = lane & 3;
    int gs = (lane >> 2) & 3;
    int h  = lane >> 4;

    int nw = gridDim.x * (blockDim.x >> 5);

    for (int b = blockIdx.x * (blockDim.x >> 5) + warp; b < nB; b += nw) {
        int base = b * BATCH;

        // lanes 0..15 hold edge (base+lane) metadata
        int eid = -1;
        if (lane < BATCH) eid = g_sorted[base + lane];
        int jj = 0, kk = 0, ii = 0;
        if (eid >= 0) { jj = ja[eid]; kk = ka[eid]; ii = ia[eid]; }

        int kb = __shfl_sync(0xffffffffu, kk, 0);   // batch-uniform k
        const float* wp = sw + kb * WKS + gs * WGS + dq * 4;

        // this lane's 8 edge rows (half h) + validity mask
        int jr[8];
        unsigned vm = 0;
        #pragma unroll
        for (int es = 0; es < 8; es++) {
            int src = h * 8 + es;
            jr[es] = __shfl_sync(0xffffffffu, jj, src);
            int ev  = __shfl_sync(0xffffffffu, eid, src);
            if (ev >= 0) vm |= (1u << es);
        }

        ulonglong2 acc[8];
        #pragma unroll
        for (int es = 0; es < 8; es++) { acc[es].x = 0ull; acc[es].y = 0ull; }

        #pragma unroll
        for (int cq = 0; cq < 4; cq++) {
            // two es-halves sharing one 4-row x buffer (register economy)
            #pragma unroll
            for (int eg = 0; eg < 2; eg++) {
                float4 xq[4];
                #pragma unroll
                for (int t = 0; t < 4; t++) {
                    int es = eg * 4 + t;
                    float4 v = make_float4(0.f, 0.f, 0.f, 0.f);
                    if (vm & (1u << es))
                        v = *(const float4*)(x + (size_t)jr[es] * IN_C + gs * 16 + cq * 4);
                    xq[t] = v;
                }
                #pragma unroll
                for (int cc = 0; cc < 4; cc++) {
                    int c = cq * 4 + cc;
                    ulonglong2 wv = *(const ulonglong2*)(wp + c * 16);  // broadcast-free LDS.128
                    #pragma unroll
                    for (int t = 0; t < 4; t++) {
                        int es = eg * 4 + t;
                        float xs = (cc == 0) ? xq[t].x : (cc == 1) ? xq[t].y
                                 : (cc == 2) ? xq[t].z : xq[t].w;
                        unsigned long long xd = pack_dup(xs);
                        acc[es].x = fma2(xd, wv.x, acc[es].x);
                        acc[es].y = fma2(xd, wv.y, acc[es].y);
                    }
                }
            }
        }

        // epilogue: one RED.128 per (lane, edge-slot); 2 edges per warp instr
        #pragma unroll
        for (int es = 0; es < 8; es++) {
            int ie = __shfl_sync(0xffffffffu, ii, h * 8 + es);
            if (vm & (1u << es)) {
                float a0, a1, a2, a3;
                unpack2(acc[es].x, a0, a1);
                unpack2(acc[es].y, a2, a3);
                atomicAdd(reinterpret_cast<float4*>(out + (size_t)ie * OUT_C + gs * 16 + dq * 4),
                          make_float4(a0, a1, a2, a3));
            }
        }
    }
}

extern "C" void kernel_launch(void* const* d_in, const int* in_sizes, int n_in,
                              void* d_out, int out_size) {
    const float* x    = (const float*)d_in[0];
    const int*   ia   = (const int*)d_in[1];
    const int*   ja   = (const int*)d_in[2];
    const int*   ka   = (const int*)d_in[3];
    // d_in[4] = n (scalar), unused: derive from sizes
    const float* wgt  = (const float*)d_in[5];
    const float* bias = (const float*)d_in[6];
    float*       out  = (float*)d_out;

    int n = in_sizes[0] / IN_C;
    int E = in_sizes[1];
    if (E > MAX_E) E = MAX_E;

    int n4   = n * (OUT_C / 4);
    int preN = E + KMAX * BATCH;                 // sentinel prefill range
    int nB   = (preN + BATCH - 1) / BATCH;
    if (nB * BATCH > preN) preN = nB * BATCH;

    int initN = (n4 > preN) ? n4 : preN;
    if (E > initN) initN = E;
    init_all<<<(initN + 255) / 256, 256>>>((float4*)out, bias, ka, n4, preN, E);
    scan_k<<<1, 32>>>();
    scatter_k<<<(E + 255) / 256, 256>>>(ka, E);

    cudaFuncSetAttribute(conv_k, cudaFuncAttributeMaxDynamicSharedMemorySize,
                         WTOT * 4);
    conv_k<<<148, 768, WTOT * 4>>>(x, ia, ja, ka, wgt, out, nB);
}

// round 7
// speedup vs baseline: 1.5234x; 1.5234x over previous
#include <cuda_runtime.h>
#include <cstdint>

#define IN_C   64
#define OUT_C  64
#define KMAX   27
#define MAX_E  2000000
#define BATCH  16
#define PADCAP (MAX_E + KMAX * BATCH + BATCH)

// weight smem layout: [k][g][c][d]; group stride padded so the per-c LDS.128
// (lanes = h*16 + gs*4 + dq) is conflict-free in each 8-lane sub-request.
#define WGS  272                 // 256 + 16 pad
#define WKS  (4 * WGS)           // 1088
#define WTOT (KMAX * WKS)        // 29376 floats = 117504 B

// ---- scratch (device globals; no allocation allowed) ----
__device__ int g_hist[KMAX];
__device__ int g_cursor[KMAX];
__device__ int g_sorted[PADCAP];   // packed: eid | (k << 24); -1 = sentinel

// ---- f32x2 helpers (packed fp32, 2 FMA/instr) ----
__device__ __forceinline__ unsigned long long pack_dup(float x) {
    unsigned long long r; unsigned xi = __float_as_uint(x);
    asm("mov.b64 %0, {%1, %1};" : "=l"(r) : "r"(xi));
    return r;
}
__device__ __forceinline__ unsigned long long fma2(unsigned long long a,
                                                   unsigned long long b,
                                                   unsigned long long c) {
    unsigned long long d;
    asm("fma.rn.f32x2 %0, %1, %2, %3;" : "=l"(d) : "l"(a), "l"(b), "l"(c));
    return d;
}
__device__ __forceinline__ void unpack2(unsigned long long v, float& lo, float& hi) {
    asm("mov.b64 {%0, %1}, %2;" : "=f"(lo), "=f"(hi) : "l"(v));
}

// ---- 1) fused: out = bias, g_sorted = -1, block-aggregated k histogram ----
__global__ void init_all(float4* __restrict__ out, const float* __restrict__ bias,
                         const int* __restrict__ ka, int n4, int preN, int E) {
    __shared__ float4 b4[16];
    __shared__ int h[KMAX];
    if (threadIdx.x < 16) b4[threadIdx.x] = reinterpret_cast<const float4*>(bias)[threadIdx.x];
    if (threadIdx.x < KMAX) h[threadIdx.x] = 0;
    __syncthreads();
    int idx = blockIdx.x * blockDim.x + threadIdx.x;
    if (idx < n4)   out[idx] = b4[idx & 15];
    if (idx < preN) g_sorted[idx] = -1;
    if (idx < E)    atomicAdd(&h[ka[idx]], 1);
    __syncthreads();
    if (threadIdx.x < KMAX && h[threadIdx.x]) atomicAdd(&g_hist[threadIdx.x], h[threadIdx.x]);
}

// ---- 2) warp exclusive scan of BATCH-aligned bucket sizes; clears g_hist ----
__global__ void scan_k() {
    int lane = threadIdx.x;
    int v = (lane < KMAX) ? ((g_hist[lane] + BATCH - 1) & ~(BATCH - 1)) : 0;
    int s = v;
    #pragma unroll
    for (int o = 1; o < 32; o <<= 1) {
        int t = __shfl_up_sync(0xffffffffu, s, o);
        if (lane >= o) s += t;
    }
    if (lane < KMAX) {
        g_cursor[lane] = s - v;   // exclusive, aligned starts
        g_hist[lane] = 0;         // reset for next graph replay
    }
}

// ---- 3) scatter packed (eid | k<<24) into k-sorted order ----
// One 256-edge tile per CTA (full grid, no grid-stride: hides sync latency).
__global__ void scatter_k(const int* __restrict__ ka, int E) {
    __shared__ int cnt[KMAX];
    __shared__ int bas[KMAX];
    int idx = blockIdx.x * blockDim.x + threadIdx.x;
    if (threadIdx.x < KMAX) cnt[threadIdx.x] = 0;
    __syncthreads();
    int kv = 0, my = 0;
    bool v = idx < E;
    if (v) { kv = ka[idx]; my = atomicAdd(&cnt[kv], 1); }
    __syncthreads();
    if (threadIdx.x < KMAX && cnt[threadIdx.x])
        bas[threadIdx.x] = atomicAdd(&g_cursor[threadIdx.x], cnt[threadIdx.x]);
    __syncthreads();
    if (v) g_sorted[bas[kv] + my] = idx | (kv << 24);
}

// ---- 4) fused conv (R2-proven structure: 512 thr, full xq[8], 128-reg budget) ----
// Warp batch = 16 edges (k-uniform by construction).
// Lane = h*16 + gs*4 + dq: owns output d-quad dq of group gs for the 8 edges
// of half h. Weights: one LDS.128 per c for the whole warp (256B distinct).
__global__ __launch_bounds__(512, 1) void conv_k(
    const float* __restrict__ x, const int* __restrict__ ia,
    const int* __restrict__ ja,
    const float* __restrict__ wgt, float* __restrict__ out, int nB)
{
    extern __shared__ float sw[];

    // cooperative weight load: src coalesced, dst scattered (once per CTA)
    for (int idx = threadIdx.x; idx < IN_C * (OUT_C / 4) * KMAX; idx += blockDim.x) {
        int k = idx % KMAX;
        int r = idx / KMAX;          // r = (g*16+c)*16 + d
        int d = r & 15;
        int c = (r >> 4) & 15;
        int g = r >> 8;
        sw[k * WKS + g * WGS + c * 16 + d] = wgt[idx];
    }
    __syncthreads();

    int lane = threadIdx.x & 31;
    int warp = threadIdx.x >> 5;
    int dq = lane & 3;
    int gs = (lane >> 2) & 3;
    int h  = lane >> 4;

    int nw = gridDim.x * (blockDim.x >> 5);

    for (int b = blockIdx.x * (blockDim.x >> 5) + warp; b < nB; b += nw) {
        int base = b * BATCH;

        // lanes 0..15 hold packed edge (base+lane) metadata
        int pk = -1;
        if (lane < BATCH) pk = g_sorted[base + lane];

        // bucket slots fill contiguously from slot 0, so a sentinel in slot 0
        // means the whole batch is empty (incl. the nB over-estimate tail).
        int p0 = __shfl_sync(0xffffffffu, pk, 0);
        if (p0 < 0) continue;
        int kb = p0 >> 24;                          // batch-uniform k, 0..26

        int jj = 0, ii = 0;
        if (pk >= 0) {
            int eid = pk & 0x00FFFFFF;
            jj = ja[eid];
            ii = ia[eid];
        }

        const float* wp = sw + kb * WKS + gs * WGS + dq * 4;

        // this lane's 8 edge rows (half h) + validity mask
        int jr[8];
        unsigned vm = 0;
        #pragma unroll
        for (int es = 0; es < 8; es++) {
            int src = h * 8 + es;
            jr[es] = __shfl_sync(0xffffffffu, jj, src);
            int ev  = __shfl_sync(0xffffffffu, pk, src);
            if (ev >= 0) vm |= (1u << es);
        }

        ulonglong2 acc[8];
        #pragma unroll
        for (int es = 0; es < 8; es++) { acc[es].x = 0ull; acc[es].y = 0ull; }

        #pragma unroll
        for (int cq = 0; cq < 4; cq++) {
            // gather x chunks: lane reads [gs*16 + cq*4 .. +3] of each of its 8 rows
            float4 xq[8];
            #pragma unroll
            for (int es = 0; es < 8; es++) {
                float4 v = make_float4(0.f, 0.f, 0.f, 0.f);
                if (vm & (1u << es))
                    v = *(const float4*)(x + (size_t)jr[es] * IN_C + gs * 16 + cq * 4);
                xq[es] = v;
            }
            #pragma unroll
            for (int cc = 0; cc < 4; cc++) {
                int c = cq * 4 + cc;
                ulonglong2 wv = *(const ulonglong2*)(wp + c * 16);  // 1 LDS.128 / warp / c
                #pragma unroll
                for (int es = 0; es < 8; es++) {
                    float xs = (cc == 0) ? xq[es].x : (cc == 1) ? xq[es].y
                             : (cc == 2) ? xq[es].z : xq[es].w;
                    unsigned long long xd = pack_dup(xs);
                    acc[es].x = fma2(xd, wv.x, acc[es].x);
                    acc[es].y = fma2(xd, wv.y, acc[es].y);
                }
            }
        }

        // epilogue: one RED.128 per (lane, edge-slot); 2 edges per warp instr
        #pragma unroll
        for (int es = 0; es < 8; es++) {
            int ie = __shfl_sync(0xffffffffu, ii, h * 8 + es);
            if (vm & (1u << es)) {
                float a0, a1, a2, a3;
                unpack2(acc[es].x, a0, a1);
                unpack2(acc[es].y, a2, a3);
                atomicAdd(reinterpret_cast<float4*>(out + (size_t)ie * OUT_C + gs * 16 + dq * 4),
                          make_float4(a0, a1, a2, a3));
            }
        }
    }
}

extern "C" void kernel_launch(void* const* d_in, const int* in_sizes, int n_in,
                              void* d_out, int out_size) {
    const float* x    = (const float*)d_in[0];
    const int*   ia   = (const int*)d_in[1];
    const int*   ja   = (const int*)d_in[2];
    const int*   ka   = (const int*)d_in[3];
    // d_in[4] = n (scalar), unused: derive from sizes
    const float* wgt  = (const float*)d_in[5];
    const float* bias = (const float*)d_in[6];
    float*       out  = (float*)d_out;

    int n = in_sizes[0] / IN_C;
    int E = in_sizes[1];
    if (E > MAX_E) E = MAX_E;

    int n4   = n * (OUT_C / 4);
    int preN = E + KMAX * BATCH;                 // sentinel prefill range
    int nB   = (preN + BATCH - 1) / BATCH;
    if (nB * BATCH > preN) preN = nB * BATCH;

    int initN = (n4 > preN) ? n4 : preN;
    if (E > initN) initN = E;
    init_all<<<(initN + 255) / 256, 256>>>((float4*)out, bias, ka, n4, preN, E);
    scan_k<<<1, 32>>>();
    scatter_k<<<(E + 255) / 256, 256>>>(ka, E);

    cudaFuncSetAttribute(conv_k, cudaFuncAttributeMaxDynamicSharedMemorySize,
                         WTOT * 4);
    conv_k<<<148, 512, WTOT * 4>>>(x, ia, ja, wgt, out, nB);
}